// round 12
// baseline (speedup 1.0000x reference)
#include <cuda_runtime.h>
#include <math.h>

// Problem constants (fixed shapes per reference)
#define B_   4
#define C_   256
#define N_   4096      // H*W
#define G_   32        // groups
#define CPG_ 8         // channels per group

// ---------------- scratch (device globals; no allocation) ----------------
__device__ float g_h  [(size_t)B_ * C_ * N_];   // groupnorm output
__device__ float g_q  [(size_t)B_ * C_ * N_];
__device__ float g_k  [(size_t)B_ * C_ * N_];
__device__ float g_v  [(size_t)B_ * C_ * N_];
__device__ float g_att[(size_t)B_ * C_ * N_];   // softmax(w) @ v
__device__ float g_w  [(size_t)B_ * N_ * N_];   // attention logits / weights (268 MB)

// ---------------- helpers ----------------
__device__ __forceinline__ float f2tf32(float x) {
    float y;
    asm("cvt.rna.tf32.f32 %0, %1;" : "=f"(y) : "f"(x));
    return y;
}

__device__ __forceinline__ void mma_tf32(float* d, const unsigned* a, const unsigned* b) {
    asm volatile(
        "mma.sync.aligned.m16n8k8.row.col.f32.tf32.tf32.f32 "
        "{%0,%1,%2,%3}, {%4,%5,%6,%7}, {%8,%9}, {%0,%1,%2,%3};"
        : "+f"(d[0]), "+f"(d[1]), "+f"(d[2]), "+f"(d[3])
        : "r"(a[0]), "r"(a[1]), "r"(a[2]), "r"(a[3]), "r"(b[0]), "r"(b[1]));
}

// ---------------- GroupNorm ----------------
__global__ __launch_bounds__(256) void gn_kernel(
    const float* __restrict__ x, const float* __restrict__ w,
    const float* __restrict__ b, float* __restrict__ out)
{
    const int bg = blockIdx.x;
    const int bb = bg / G_;
    const int g  = bg % G_;
    const float* xp = x   + ((size_t)bb * C_ + (size_t)g * CPG_) * N_;
    float*       op = out + ((size_t)bb * C_ + (size_t)g * CPG_) * N_;
    const int NE = CPG_ * N_;  // 32768

    float s = 0.f, ss = 0.f;
    for (int i = threadIdx.x; i < NE; i += 256) {
        float v = xp[i];
        s += v; ss += v * v;
    }
    __shared__ float rs[8], rss[8];
    #pragma unroll
    for (int o = 16; o; o >>= 1) {
        s  += __shfl_xor_sync(0xffffffffu, s,  o);
        ss += __shfl_xor_sync(0xffffffffu, ss, o);
    }
    if ((threadIdx.x & 31) == 0) { rs[threadIdx.x >> 5] = s; rss[threadIdx.x >> 5] = ss; }
    __syncthreads();
    s = 0.f; ss = 0.f;
    #pragma unroll
    for (int i = 0; i < 8; i++) { s += rs[i]; ss += rss[i]; }

    const float invn = 1.0f / (float)NE;
    const float mean = s * invn;
    const float var  = ss * invn - mean * mean;
    const float inv  = rsqrtf(var + 1e-5f);

    for (int i = threadIdx.x; i < NE; i += 256) {
        int c = g * CPG_ + i / N_;
        op[i] = (xp[i] - mean) * inv * w[c] + b[c];
    }
}

// ---------------- tf32 tensor-core GEMM ----------------
// TRANS=0 ("kk"):  C[m][n] = epi( sum_k A[k][m] * B[k][n] )   (k-major operands)
// TRANS=1 ("nt"):  C[m][n] = epi( sum_k A[m][k] * B[n][k] )   (k-contiguous rows)
// EPI: 0 = +bias[m] ; 1 = *scale ; 2 = (acc + bias[m] + res[m][n]) * scale
// Block tile 128x128, k-tile 16, 256 threads = 8 warps (2M x 4N), warp 64x32.
#define PITCH 136

template<int TRANS, int EPI>
__global__ __launch_bounds__(256, 2) void mma_gemm(
    const float* __restrict__ A, const float* __restrict__ B,
    float* __restrict__ C, const float* __restrict__ bias,
    const float* __restrict__ res,
    size_t aStride, size_t bStride, size_t cStride,
    int lda, int ldb, int ldc, int K, float scale)
{
    A += (size_t)blockIdx.z * aStride;
    B += (size_t)blockIdx.z * bStride;
    C += (size_t)blockIdx.z * cStride;
    if (EPI == 2) res += (size_t)blockIdx.z * cStride;

    __shared__ float As[2][16][PITCH];
    __shared__ float Bs[2][16][PITCH];

    const int tid  = threadIdx.x;
    const int lane = tid & 31;
    const int warp = tid >> 5;
    const int g = lane >> 2;        // 0..7
    const int t = lane & 3;         // 0..3
    const int wm = (warp & 1) * 64; // warp M offset
    const int wn = (warp >> 1) * 32;// warp N offset
    const int m0 = blockIdx.y * 128;
    const int n0 = blockIdx.x * 128;

    float acc[4][4][4] = {};
    float4 ra0, ra1, rb0, rb1;

    // loader coordinates
    int sk, sm;
    const float *Ap, *Bp;
    if (TRANS == 0) {
        sk = tid >> 5;            // k row 0..7 (also +8)
        sm = (tid & 31) * 4;      // m/n column (float4)
        Ap = A + (size_t)sk * lda + m0 + sm;
        Bp = B + (size_t)sk * ldb + n0 + sm;
    } else {
        sm = tid >> 1;            // tile row 0..127
        sk = (tid & 1) * 8;       // k base 0 or 8
        Ap = A + (size_t)(m0 + sm) * lda + sk;
        Bp = B + (size_t)(n0 + sm) * ldb + sk;
    }

    auto gload = [&]() {
        if (TRANS == 0) {
            ra0 = *(const float4*)Ap;
            ra1 = *(const float4*)(Ap + (size_t)8 * lda);
            rb0 = *(const float4*)Bp;
            rb1 = *(const float4*)(Bp + (size_t)8 * ldb);
            Ap += (size_t)16 * lda;
            Bp += (size_t)16 * ldb;
        } else {
            ra0 = *(const float4*)Ap;
            ra1 = *(const float4*)(Ap + 4);
            rb0 = *(const float4*)Bp;
            rb1 = *(const float4*)(Bp + 4);
            Ap += 16; Bp += 16;
        }
    };
    auto sstore = [&](int buf) {
        if (TRANS == 0) {
            *(float4*)&As[buf][sk    ][sm] = make_float4(f2tf32(ra0.x), f2tf32(ra0.y), f2tf32(ra0.z), f2tf32(ra0.w));
            *(float4*)&As[buf][sk + 8][sm] = make_float4(f2tf32(ra1.x), f2tf32(ra1.y), f2tf32(ra1.z), f2tf32(ra1.w));
            *(float4*)&Bs[buf][sk    ][sm] = make_float4(f2tf32(rb0.x), f2tf32(rb0.y), f2tf32(rb0.z), f2tf32(rb0.w));
            *(float4*)&Bs[buf][sk + 8][sm] = make_float4(f2tf32(rb1.x), f2tf32(rb1.y), f2tf32(rb1.z), f2tf32(rb1.w));
        } else {
            As[buf][sk + 0][sm] = f2tf32(ra0.x);
            As[buf][sk + 1][sm] = f2tf32(ra0.y);
            As[buf][sk + 2][sm] = f2tf32(ra0.z);
            As[buf][sk + 3][sm] = f2tf32(ra0.w);
            As[buf][sk + 4][sm] = f2tf32(ra1.x);
            As[buf][sk + 5][sm] = f2tf32(ra1.y);
            As[buf][sk + 6][sm] = f2tf32(ra1.z);
            As[buf][sk + 7][sm] = f2tf32(ra1.w);
            Bs[buf][sk + 0][sm] = f2tf32(rb0.x);
            Bs[buf][sk + 1][sm] = f2tf32(rb0.y);
            Bs[buf][sk + 2][sm] = f2tf32(rb0.z);
            Bs[buf][sk + 3][sm] = f2tf32(rb0.w);
            Bs[buf][sk + 4][sm] = f2tf32(rb1.x);
            Bs[buf][sk + 5][sm] = f2tf32(rb1.y);
            Bs[buf][sk + 6][sm] = f2tf32(rb1.z);
            Bs[buf][sk + 7][sm] = f2tf32(rb1.w);
        }
    };

    const int nIt = K >> 4;
    gload();
    sstore(0);
    __syncthreads();

    for (int it = 0; it < nIt; ++it) {
        const int buf = it & 1;
        if (it + 1 < nIt) gload();

        #pragma unroll
        for (int s = 0; s < 2; ++s) {
            const int kb = s * 8;
            unsigned af[4][4], bf[4][2];
            #pragma unroll
            for (int j = 0; j < 4; ++j) {
                bf[j][0] = __float_as_uint(Bs[buf][kb + t    ][wn + j * 8 + g]);
                bf[j][1] = __float_as_uint(Bs[buf][kb + t + 4][wn + j * 8 + g]);
            }
            #pragma unroll
            for (int i = 0; i < 4; ++i) {
                const int mb = wm + i * 16;
                af[i][0] = __float_as_uint(As[buf][kb + t    ][mb + g]);
                af[i][1] = __float_as_uint(As[buf][kb + t    ][mb + g + 8]);
                af[i][2] = __float_as_uint(As[buf][kb + t + 4][mb + g]);
                af[i][3] = __float_as_uint(As[buf][kb + t + 4][mb + g + 8]);
            }
            #pragma unroll
            for (int i = 0; i < 4; ++i)
                #pragma unroll
                for (int j = 0; j < 4; ++j)
                    mma_tf32(acc[i][j], af[i], bf[j]);
        }

        if (it + 1 < nIt) {
            sstore(buf ^ 1);
            __syncthreads();
        }
    }

    // epilogue
    #pragma unroll
    for (int i = 0; i < 4; ++i) {
        const int r0 = m0 + wm + i * 16 + g;
        const int r1 = r0 + 8;
        float bv0 = 0.f, bv1 = 0.f;
        if (EPI != 1) { bv0 = bias[r0]; bv1 = bias[r1]; }
        #pragma unroll
        for (int j = 0; j < 4; ++j) {
            const int cc = n0 + wn + j * 8 + 2 * t;
            const float* d = acc[i][j];
            if (EPI == 0) {
                *(float2*)&C[(size_t)r0 * ldc + cc] = make_float2(d[0] + bv0, d[1] + bv0);
                *(float2*)&C[(size_t)r1 * ldc + cc] = make_float2(d[2] + bv1, d[3] + bv1);
            } else if (EPI == 1) {
                *(float2*)&C[(size_t)r0 * ldc + cc] = make_float2(d[0] * scale, d[1] * scale);
                *(float2*)&C[(size_t)r1 * ldc + cc] = make_float2(d[2] * scale, d[3] * scale);
            } else {
                const float2 x0 = *(const float2*)&res[(size_t)r0 * ldc + cc];
                const float2 x1 = *(const float2*)&res[(size_t)r1 * ldc + cc];
                *(float2*)&C[(size_t)r0 * ldc + cc] =
                    make_float2((d[0] + bv0 + x0.x) * scale, (d[1] + bv0 + x0.y) * scale);
                *(float2*)&C[(size_t)r1 * ldc + cc] =
                    make_float2((d[2] + bv1 + x1.x) * scale, (d[3] + bv1 + x1.y) * scale);
            }
        }
    }
}

// ---------------- Row softmax over N_=4096, in place. One block per row.
__global__ __launch_bounds__(256) void softmax_kernel(float* __restrict__ w)
{
    __shared__ float buf[N_];
    __shared__ float red[8];
    float* p = w + (size_t)blockIdx.x * N_;
    const int t = threadIdx.x;

    float mx = -1e30f;
    for (int i = t; i < N_; i += 256) { float v = p[i]; buf[i] = v; mx = fmaxf(mx, v); }
    #pragma unroll
    for (int o = 16; o; o >>= 1) mx = fmaxf(mx, __shfl_xor_sync(0xffffffffu, mx, o));
    if ((t & 31) == 0) red[t >> 5] = mx;
    __syncthreads();
    mx = red[0];
    #pragma unroll
    for (int i = 1; i < 8; i++) mx = fmaxf(mx, red[i]);

    float s = 0.f;
    for (int i = t; i < N_; i += 256) { float e = __expf(buf[i] - mx); buf[i] = e; s += e; }
    #pragma unroll
    for (int o = 16; o; o >>= 1) s += __shfl_xor_sync(0xffffffffu, s, o);
    __syncthreads();
    if ((t & 31) == 0) red[t >> 5] = s;
    __syncthreads();
    s = 0.f;
    #pragma unroll
    for (int i = 0; i < 8; i++) s += red[i];

    const float inv = 1.f / s;
    for (int i = t; i < N_; i += 256) p[i] = buf[i] * inv;
}

// ---------------- launch ----------------
extern "C" void kernel_launch(void* const* d_in, const int* in_sizes, int n_in,
                              void* d_out, int out_size)
{
    const float* x    = (const float*)d_in[0];
    const float* gn_w = (const float*)d_in[1];
    const float* gn_b = (const float*)d_in[2];
    const float* Wq   = (const float*)d_in[3];
    const float* bq   = (const float*)d_in[4];
    const float* Wk   = (const float*)d_in[5];
    const float* bk   = (const float*)d_in[6];
    const float* Wv   = (const float*)d_in[7];
    const float* bv   = (const float*)d_in[8];
    const float* Wp   = (const float*)d_in[9];
    const float* bp   = (const float*)d_in[10];
    float* out = (float*)d_out;

    float *ph, *pq, *pk, *pv, *patt, *pw;
    cudaGetSymbolAddress((void**)&ph,   g_h);
    cudaGetSymbolAddress((void**)&pq,   g_q);
    cudaGetSymbolAddress((void**)&pk,   g_k);
    cudaGetSymbolAddress((void**)&pv,   g_v);
    cudaGetSymbolAddress((void**)&patt, g_att);
    cudaGetSymbolAddress((void**)&pw,   g_w);

    const size_t chw = (size_t)C_ * N_;   // per-batch [C, HW]
    const size_t nn  = (size_t)N_ * N_;   // per-batch logits

    // 1) GroupNorm
    gn_kernel<<<B_ * G_, 256>>>(x, gn_w, gn_b, ph);

    // 2) Q, K, V projections: q[d][n] = sum_c W[c][d] * h[c][n] + b[d]
    {
        dim3 grid(N_ / 128, C_ / 128, B_);
        mma_gemm<0, 0><<<grid, 256>>>(Wq, ph, pq, bq, nullptr, 0, chw, chw,
                                      C_, N_, N_, C_, 0.f);
        mma_gemm<0, 0><<<grid, 256>>>(Wk, ph, pk, bk, nullptr, 0, chw, chw,
                                      C_, N_, N_, C_, 0.f);
        mma_gemm<0, 0><<<grid, 256>>>(Wv, ph, pv, bv, nullptr, 0, chw, chw,
                                      C_, N_, N_, C_, 0.f);
    }

    // 3) logits: w[n][m] = (1/16) * sum_c q[c][n] * k[c][m]
    {
        dim3 grid(N_ / 128, N_ / 128, B_);
        mma_gemm<0, 1><<<grid, 256>>>(pq, pk, pw, nullptr, nullptr, chw, chw, nn,
                                      N_, N_, N_, C_, 0.0625f);
    }

    // 4) softmax rows (in place)
    softmax_kernel<<<B_ * N_, 256>>>(pw);

    // 5) att[c][n] = sum_m v[c][m] * w[n][m]   (k = spatial m)
    {
        dim3 grid(N_ / 128, C_ / 128, B_);
        mma_gemm<1, 1><<<grid, 256>>>(pv, pw, patt, nullptr, nullptr, chw, nn, chw,
                                      N_, N_, N_, N_, 1.0f);
    }

    // 6) out = (x + Wp^T att + bp) / sqrt(2)
    {
        dim3 grid(N_ / 128, C_ / 128, B_);
        mma_gemm<0, 2><<<grid, 256>>>(Wp, patt, out, bp, x, 0, chw, chw,
                                      C_, N_, N_, C_, 0.70710678118654752f);
    }
}

// round 13
// speedup vs baseline: 1.0012x; 1.0012x over previous
#include <cuda_runtime.h>
#include <math.h>

// Problem constants (fixed shapes per reference)
#define B_   4
#define C_   256
#define N_   4096      // H*W
#define G_   32        // groups
#define CPG_ 8         // channels per group

// ---------------- scratch (device globals; no allocation) ----------------
__device__ float g_h  [(size_t)B_ * C_ * N_];   // groupnorm output
__device__ float g_q  [(size_t)B_ * C_ * N_];
__device__ float g_k  [(size_t)B_ * C_ * N_];
__device__ float g_v  [(size_t)B_ * C_ * N_];
__device__ float g_att[(size_t)B_ * C_ * N_];   // softmax(w) @ v
__device__ float g_w  [(size_t)B_ * N_ * N_];   // attention logits / weights (268 MB)

// ---------------- helpers ----------------
__device__ __forceinline__ float f2tf32(float x) {
    float y;
    asm("cvt.rna.tf32.f32 %0, %1;" : "=f"(y) : "f"(x));
    return y;
}

__device__ __forceinline__ void mma_tf32(float* d, const unsigned* a, const unsigned* b) {
    asm volatile(
        "mma.sync.aligned.m16n8k8.row.col.f32.tf32.tf32.f32 "
        "{%0,%1,%2,%3}, {%4,%5,%6,%7}, {%8,%9}, {%0,%1,%2,%3};"
        : "+f"(d[0]), "+f"(d[1]), "+f"(d[2]), "+f"(d[3])
        : "r"(a[0]), "r"(a[1]), "r"(a[2]), "r"(a[3]), "r"(b[0]), "r"(b[1]));
}

// ---------------- GroupNorm ----------------
__global__ __launch_bounds__(256) void gn_kernel(
    const float* __restrict__ x, const float* __restrict__ w,
    const float* __restrict__ b, float* __restrict__ out)
{
    const int bg = blockIdx.x;
    const int bb = bg / G_;
    const int g  = bg % G_;
    const float* xp = x   + ((size_t)bb * C_ + (size_t)g * CPG_) * N_;
    float*       op = out + ((size_t)bb * C_ + (size_t)g * CPG_) * N_;
    const int NE = CPG_ * N_;  // 32768

    float s = 0.f, ss = 0.f;
    for (int i = threadIdx.x; i < NE; i += 256) {
        float v = xp[i];
        s += v; ss += v * v;
    }
    __shared__ float rs[8], rss[8];
    #pragma unroll
    for (int o = 16; o; o >>= 1) {
        s  += __shfl_xor_sync(0xffffffffu, s,  o);
        ss += __shfl_xor_sync(0xffffffffu, ss, o);
    }
    if ((threadIdx.x & 31) == 0) { rs[threadIdx.x >> 5] = s; rss[threadIdx.x >> 5] = ss; }
    __syncthreads();
    s = 0.f; ss = 0.f;
    #pragma unroll
    for (int i = 0; i < 8; i++) { s += rs[i]; ss += rss[i]; }

    const float invn = 1.0f / (float)NE;
    const float mean = s * invn;
    const float var  = ss * invn - mean * mean;
    const float inv  = rsqrtf(var + 1e-5f);

    for (int i = threadIdx.x; i < NE; i += 256) {
        int c = g * CPG_ + i / N_;
        op[i] = (xp[i] - mean) * inv * w[c] + b[c];
    }
}

// ---------------- tf32 tensor-core GEMM ----------------
// TRANS=0 ("kk"):  C[m][n] = epi( sum_k A[k][m] * B[k][n] )   (k-major operands)
// TRANS=1 ("nt"):  C[m][n] = epi( sum_k A[m][k] * B[n][k] )   (k-contiguous rows)
// EPI: 0 = +bias[m] ; 1 = *scale ; 2 = (acc + bias[m] + res[m][n]) * scale
// Block tile 128x128, k-tile 16, 256 threads = 8 warps (2M x 4N), warp 64x32.
#define PITCH 136

template<int TRANS, int EPI>
__global__ __launch_bounds__(256, 2) void mma_gemm(
    const float* __restrict__ A, const float* __restrict__ B,
    float* __restrict__ C, const float* __restrict__ bias,
    const float* __restrict__ res,
    size_t aStride, size_t bStride, size_t cStride,
    int lda, int ldb, int ldc, int K, float scale)
{
    A += (size_t)blockIdx.z * aStride;
    B += (size_t)blockIdx.z * bStride;
    C += (size_t)blockIdx.z * cStride;
    if (EPI == 2) res += (size_t)blockIdx.z * cStride;

    __shared__ float As[2][16][PITCH];
    __shared__ float Bs[2][16][PITCH];

    const int tid  = threadIdx.x;
    const int lane = tid & 31;
    const int warp = tid >> 5;
    const int g = lane >> 2;        // 0..7
    const int t = lane & 3;         // 0..3
    const int wm = (warp & 1) * 64; // warp M offset
    const int wn = (warp >> 1) * 32;// warp N offset
    const int m0 = blockIdx.y * 128;
    const int n0 = blockIdx.x * 128;

    float acc[4][4][4] = {};
    float4 ra0, ra1, rb0, rb1;

    // loader coordinates
    int sk, sm;
    const float *Ap, *Bp;
    if (TRANS == 0) {
        sk = tid >> 5;            // k row 0..7 (also +8)
        sm = (tid & 31) * 4;      // m/n column (float4)
        Ap = A + (size_t)sk * lda + m0 + sm;
        Bp = B + (size_t)sk * ldb + n0 + sm;
    } else {
        sm = tid >> 1;            // tile row 0..127
        sk = (tid & 1) * 8;       // k base 0 or 8
        Ap = A + (size_t)(m0 + sm) * lda + sk;
        Bp = B + (size_t)(n0 + sm) * ldb + sk;
    }

    auto gload = [&]() {
        if (TRANS == 0) {
            ra0 = *(const float4*)Ap;
            ra1 = *(const float4*)(Ap + (size_t)8 * lda);
            rb0 = *(const float4*)Bp;
            rb1 = *(const float4*)(Bp + (size_t)8 * ldb);
            Ap += (size_t)16 * lda;
            Bp += (size_t)16 * ldb;
        } else {
            ra0 = *(const float4*)Ap;
            ra1 = *(const float4*)(Ap + 4);
            rb0 = *(const float4*)Bp;
            rb1 = *(const float4*)(Bp + 4);
            Ap += 16; Bp += 16;
        }
    };
    auto sstore = [&](int buf) {
        if (TRANS == 0) {
            *(float4*)&As[buf][sk    ][sm] = make_float4(f2tf32(ra0.x), f2tf32(ra0.y), f2tf32(ra0.z), f2tf32(ra0.w));
            *(float4*)&As[buf][sk + 8][sm] = make_float4(f2tf32(ra1.x), f2tf32(ra1.y), f2tf32(ra1.z), f2tf32(ra1.w));
            *(float4*)&Bs[buf][sk    ][sm] = make_float4(f2tf32(rb0.x), f2tf32(rb0.y), f2tf32(rb0.z), f2tf32(rb0.w));
            *(float4*)&Bs[buf][sk + 8][sm] = make_float4(f2tf32(rb1.x), f2tf32(rb1.y), f2tf32(rb1.z), f2tf32(rb1.w));
        } else {
            As[buf][sk + 0][sm] = f2tf32(ra0.x);
            As[buf][sk + 1][sm] = f2tf32(ra0.y);
            As[buf][sk + 2][sm] = f2tf32(ra0.z);
            As[buf][sk + 3][sm] = f2tf32(ra0.w);
            As[buf][sk + 4][sm] = f2tf32(ra1.x);
            As[buf][sk + 5][sm] = f2tf32(ra1.y);
            As[buf][sk + 6][sm] = f2tf32(ra1.z);
            As[buf][sk + 7][sm] = f2tf32(ra1.w);
            Bs[buf][sk + 0][sm] = f2tf32(rb0.x);
            Bs[buf][sk + 1][sm] = f2tf32(rb0.y);
            Bs[buf][sk + 2][sm] = f2tf32(rb0.z);
            Bs[buf][sk + 3][sm] = f2tf32(rb0.w);
            Bs[buf][sk + 4][sm] = f2tf32(rb1.x);
            Bs[buf][sk + 5][sm] = f2tf32(rb1.y);
            Bs[buf][sk + 6][sm] = f2tf32(rb1.z);
            Bs[buf][sk + 7][sm] = f2tf32(rb1.w);
        }
    };

    const int nIt = K >> 4;
    gload();
    sstore(0);
    __syncthreads();

    for (int it = 0; it < nIt; ++it) {
        const int buf = it & 1;
        if (it + 1 < nIt) gload();

        #pragma unroll
        for (int s = 0; s < 2; ++s) {
            const int kb = s * 8;
            unsigned af[4][4], bf[4][2];
            #pragma unroll
            for (int j = 0; j < 4; ++j) {
                bf[j][0] = __float_as_uint(Bs[buf][kb + t    ][wn + j * 8 + g]);
                bf[j][1] = __float_as_uint(Bs[buf][kb + t + 4][wn + j * 8 + g]);
            }
            #pragma unroll
            for (int i = 0; i < 4; ++i) {
                const int mb = wm + i * 16;
                af[i][0] = __float_as_uint(As[buf][kb + t    ][mb + g]);
                af[i][1] = __float_as_uint(As[buf][kb + t    ][mb + g + 8]);
                af[i][2] = __float_as_uint(As[buf][kb + t + 4][mb + g]);
                af[i][3] = __float_as_uint(As[buf][kb + t + 4][mb + g + 8]);
            }
            #pragma unroll
            for (int i = 0; i < 4; ++i)
                #pragma unroll
                for (int j = 0; j < 4; ++j)
                    mma_tf32(acc[i][j], af[i], bf[j]);
        }

        if (it + 1 < nIt) {
            sstore(buf ^ 1);
            __syncthreads();
        }
    }

    // epilogue
    #pragma unroll
    for (int i = 0; i < 4; ++i) {
        const int r0 = m0 + wm + i * 16 + g;
        const int r1 = r0 + 8;
        float bv0 = 0.f, bv1 = 0.f;
        if (EPI != 1) { bv0 = bias[r0]; bv1 = bias[r1]; }
        #pragma unroll
        for (int j = 0; j < 4; ++j) {
            const int cc = n0 + wn + j * 8 + 2 * t;
            const float* d = acc[i][j];
            if (EPI == 0) {
                *(float2*)&C[(size_t)r0 * ldc + cc] = make_float2(d[0] + bv0, d[1] + bv0);
                *(float2*)&C[(size_t)r1 * ldc + cc] = make_float2(d[2] + bv1, d[3] + bv1);
            } else if (EPI == 1) {
                *(float2*)&C[(size_t)r0 * ldc + cc] = make_float2(d[0] * scale, d[1] * scale);
                *(float2*)&C[(size_t)r1 * ldc + cc] = make_float2(d[2] * scale, d[3] * scale);
            } else {
                const float2 x0 = *(const float2*)&res[(size_t)r0 * ldc + cc];
                const float2 x1 = *(const float2*)&res[(size_t)r1 * ldc + cc];
                *(float2*)&C[(size_t)r0 * ldc + cc] =
                    make_float2((d[0] + bv0 + x0.x) * scale, (d[1] + bv0 + x0.y) * scale);
                *(float2*)&C[(size_t)r1 * ldc + cc] =
                    make_float2((d[2] + bv1 + x1.x) * scale, (d[3] + bv1 + x1.y) * scale);
            }
        }
    }
}

// ---------------- Row softmax over N_=4096, in place. One block per row.
__global__ __launch_bounds__(256) void softmax_kernel(float* __restrict__ w)
{
    __shared__ float buf[N_];
    __shared__ float red[8];
    float* p = w + (size_t)blockIdx.x * N_;
    const int t = threadIdx.x;

    float mx = -1e30f;
    for (int i = t; i < N_; i += 256) { float v = p[i]; buf[i] = v; mx = fmaxf(mx, v); }
    #pragma unroll
    for (int o = 16; o; o >>= 1) mx = fmaxf(mx, __shfl_xor_sync(0xffffffffu, mx, o));
    if ((t & 31) == 0) red[t >> 5] = mx;
    __syncthreads();
    mx = red[0];
    #pragma unroll
    for (int i = 1; i < 8; i++) mx = fmaxf(mx, red[i]);

    float s = 0.f;
    for (int i = t; i < N_; i += 256) { float e = __expf(buf[i] - mx); buf[i] = e; s += e; }
    #pragma unroll
    for (int o = 16; o; o >>= 1) s += __shfl_xor_sync(0xffffffffu, s, o);
    __syncthreads();
    if ((t & 31) == 0) red[t >> 5] = s;
    __syncthreads();
    s = 0.f;
    #pragma unroll
    for (int i = 0; i < 8; i++) s += red[i];

    const float inv = 1.f / s;
    for (int i = t; i < N_; i += 256) p[i] = buf[i] * inv;
}

// ---------------- launch ----------------
extern "C" void kernel_launch(void* const* d_in, const int* in_sizes, int n_in,
                              void* d_out, int out_size)
{
    const float* x    = (const float*)d_in[0];
    const float* gn_w = (const float*)d_in[1];
    const float* gn_b = (const float*)d_in[2];
    const float* Wq   = (const float*)d_in[3];
    const float* bq   = (const float*)d_in[4];
    const float* Wk   = (const float*)d_in[5];
    const float* bk   = (const float*)d_in[6];
    const float* Wv   = (const float*)d_in[7];
    const float* bv   = (const float*)d_in[8];
    const float* Wp   = (const float*)d_in[9];
    const float* bp   = (const float*)d_in[10];
    float* out = (float*)d_out;

    float *ph, *pq, *pk, *pv, *patt, *pw;
    cudaGetSymbolAddress((void**)&ph,   g_h);
    cudaGetSymbolAddress((void**)&pq,   g_q);
    cudaGetSymbolAddress((void**)&pk,   g_k);
    cudaGetSymbolAddress((void**)&pv,   g_v);
    cudaGetSymbolAddress((void**)&patt, g_att);
    cudaGetSymbolAddress((void**)&pw,   g_w);

    const size_t chw = (size_t)C_ * N_;   // per-batch [C, HW]
    const size_t nn  = (size_t)N_ * N_;   // per-batch logits

    // 1) GroupNorm
    gn_kernel<<<B_ * G_, 256>>>(x, gn_w, gn_b, ph);

    // 2) Q, K, V projections: q[d][n] = sum_c W[c][d] * h[c][n] + b[d]
    {
        dim3 grid(N_ / 128, C_ / 128, B_);
        mma_gemm<0, 0><<<grid, 256>>>(Wq, ph, pq, bq, nullptr, 0, chw, chw,
                                      C_, N_, N_, C_, 0.f);
        mma_gemm<0, 0><<<grid, 256>>>(Wk, ph, pk, bk, nullptr, 0, chw, chw,
                                      C_, N_, N_, C_, 0.f);
        mma_gemm<0, 0><<<grid, 256>>>(Wv, ph, pv, bv, nullptr, 0, chw, chw,
                                      C_, N_, N_, C_, 0.f);
    }

    // 3) logits: w[n][m] = (1/16) * sum_c q[c][n] * k[c][m]
    {
        dim3 grid(N_ / 128, N_ / 128, B_);
        mma_gemm<0, 1><<<grid, 256>>>(pq, pk, pw, nullptr, nullptr, chw, chw, nn,
                                      N_, N_, N_, C_, 0.0625f);
    }

    // 4) softmax rows (in place)
    softmax_kernel<<<B_ * N_, 256>>>(pw);

    // 5) att[c][n] = sum_m v[c][m] * w[n][m]   (k = spatial m)
    {
        dim3 grid(N_ / 128, C_ / 128, B_);
        mma_gemm<1, 1><<<grid, 256>>>(pv, pw, patt, nullptr, nullptr, chw, nn, chw,
                                      N_, N_, N_, N_, 1.0f);
    }

    // 6) out = (x + Wp^T att + bp) / sqrt(2)
    {
        dim3 grid(N_ / 128, C_ / 128, B_);
        mma_gemm<0, 2><<<grid, 256>>>(Wp, patt, out, bp, x, 0, chw, chw,
                                      C_, N_, N_, C_, 0.70710678118654752f);
    }
}

// round 14
// speedup vs baseline: 1.4850x; 1.4832x over previous
#include <cuda_runtime.h>
#include <cuda_bf16.h>
#include <math.h>

// Problem constants (fixed shapes per reference)
#define B_   4
#define C_   256
#define N_   4096      // H*W
#define G_   32        // groups
#define CPG_ 8         // channels per group

// ---------------- scratch (device globals; no allocation) ----------------
__device__ float g_h  [(size_t)B_ * C_ * N_];   // groupnorm output
__device__ float g_q  [(size_t)B_ * C_ * N_];
__device__ float g_k  [(size_t)B_ * C_ * N_];
__device__ float g_v  [(size_t)B_ * C_ * N_];
__device__ float g_att[(size_t)B_ * C_ * N_];   // softmax(w) @ v
__device__ float g_w  [(size_t)B_ * N_ * N_];   // attention logits / weights (268 MB)

// ---------------- helpers ----------------
// pack two fp32 -> bf16x2 (lo = first/even-k, hi = second/odd-k)
__device__ __forceinline__ unsigned pack_bf2(float lo, float hi) {
    __nv_bfloat162 h = __float22bfloat162_rn(make_float2(lo, hi));
    return *reinterpret_cast<unsigned*>(&h);
}

__device__ __forceinline__ void mma_bf16(float* d, const unsigned* a, const unsigned* b) {
    asm volatile(
        "mma.sync.aligned.m16n8k16.row.col.f32.bf16.bf16.f32 "
        "{%0,%1,%2,%3}, {%4,%5,%6,%7}, {%8,%9}, {%0,%1,%2,%3};"
        : "+f"(d[0]), "+f"(d[1]), "+f"(d[2]), "+f"(d[3])
        : "r"(a[0]), "r"(a[1]), "r"(a[2]), "r"(a[3]), "r"(b[0]), "r"(b[1]));
}

// ---------------- GroupNorm ----------------
__global__ __launch_bounds__(256) void gn_kernel(
    const float* __restrict__ x, const float* __restrict__ w,
    const float* __restrict__ b, float* __restrict__ out)
{
    const int bg = blockIdx.x;
    const int bb = bg / G_;
    const int g  = bg % G_;
    const float* xp = x   + ((size_t)bb * C_ + (size_t)g * CPG_) * N_;
    float*       op = out + ((size_t)bb * C_ + (size_t)g * CPG_) * N_;
    const int NE = CPG_ * N_;  // 32768

    float s = 0.f, ss = 0.f;
    for (int i = threadIdx.x; i < NE; i += 256) {
        float v = xp[i];
        s += v; ss += v * v;
    }
    __shared__ float rs[8], rss[8];
    #pragma unroll
    for (int o = 16; o; o >>= 1) {
        s  += __shfl_xor_sync(0xffffffffu, s,  o);
        ss += __shfl_xor_sync(0xffffffffu, ss, o);
    }
    if ((threadIdx.x & 31) == 0) { rs[threadIdx.x >> 5] = s; rss[threadIdx.x >> 5] = ss; }
    __syncthreads();
    s = 0.f; ss = 0.f;
    #pragma unroll
    for (int i = 0; i < 8; i++) { s += rs[i]; ss += rss[i]; }

    const float invn = 1.0f / (float)NE;
    const float mean = s * invn;
    const float var  = ss * invn - mean * mean;
    const float inv  = rsqrtf(var + 1e-5f);

    for (int i = threadIdx.x; i < NE; i += 256) {
        int c = g * CPG_ + i / N_;
        op[i] = (xp[i] - mean) * inv * w[c] + b[c];
    }
}

// ---------------- bf16 tensor-core GEMM ----------------
// TRANS=0 ("kk"):  C[m][n] = epi( sum_k A[k][m] * B[k][n] )   (k-major operands)
// TRANS=1 ("nt"):  C[m][n] = epi( sum_k A[m][k] * B[n][k] )   (k-contiguous rows)
// EPI: 0 = +bias[m] ; 1 = *scale ; 2 = (acc + bias[m] + res[m][n]) * scale
// Block tile 128x128, k-tile 32, 256 threads = 8 warps (2M x 4N), warp 64x32.
// Smem holds bf16 pairs packed in uint32 at [kpair][m], pitch 136 (conflict-free:
// fragment bank = 8t+g, bijective over the warp).
#define PITCH 136

template<int TRANS, int EPI>
__global__ __launch_bounds__(256, 2) void mma_gemm(
    const float* __restrict__ A, const float* __restrict__ B,
    float* __restrict__ C, const float* __restrict__ bias,
    const float* __restrict__ res,
    size_t aStride, size_t bStride, size_t cStride,
    int lda, int ldb, int ldc, int K, float scale)
{
    A += (size_t)blockIdx.z * aStride;
    B += (size_t)blockIdx.z * bStride;
    C += (size_t)blockIdx.z * cStride;
    if (EPI == 2) res += (size_t)blockIdx.z * cStride;

    __shared__ unsigned As[2][16][PITCH];   // 16 kpairs (k-tile 32)
    __shared__ unsigned Bs[2][16][PITCH];

    const int tid  = threadIdx.x;
    const int lane = tid & 31;
    const int warp = tid >> 5;
    const int g = lane >> 2;        // 0..7
    const int t = lane & 3;         // 0..3
    const int wm = (warp & 1) * 64; // warp M offset
    const int wn = (warp >> 1) * 32;// warp N offset
    const int m0 = blockIdx.y * 128;
    const int n0 = blockIdx.x * 128;

    float acc[4][4][4] = {};
    float4 ra0, ra1, ra2, ra3, rb0, rb1, rb2, rb3;

    // loader coordinates
    int sk, sm;
    const float *Ap, *Bp;
    if (TRANS == 0) {
        sk = tid >> 5;            // kpair row 0..7 (also +8)
        sm = (tid & 31) * 4;      // m/n column (float4)
        Ap = A + (size_t)(2 * sk) * lda + m0 + sm;
        Bp = B + (size_t)(2 * sk) * ldb + n0 + sm;
    } else {
        sm = tid >> 1;            // tile row 0..127
        sk = (tid & 1) * 16;      // k base 0 or 16
        Ap = A + (size_t)(m0 + sm) * lda + sk;
        Bp = B + (size_t)(n0 + sm) * ldb + sk;
    }

    auto gload = [&]() {
        if (TRANS == 0) {
            ra0 = *(const float4*)Ap;
            ra1 = *(const float4*)(Ap + (size_t)lda);
            ra2 = *(const float4*)(Ap + (size_t)16 * lda);
            ra3 = *(const float4*)(Ap + (size_t)17 * lda);
            rb0 = *(const float4*)Bp;
            rb1 = *(const float4*)(Bp + (size_t)ldb);
            rb2 = *(const float4*)(Bp + (size_t)16 * ldb);
            rb3 = *(const float4*)(Bp + (size_t)17 * ldb);
            Ap += (size_t)32 * lda;
            Bp += (size_t)32 * ldb;
        } else {
            ra0 = *(const float4*)Ap;
            ra1 = *(const float4*)(Ap + 4);
            ra2 = *(const float4*)(Ap + 8);
            ra3 = *(const float4*)(Ap + 12);
            rb0 = *(const float4*)Bp;
            rb1 = *(const float4*)(Bp + 4);
            rb2 = *(const float4*)(Bp + 8);
            rb3 = *(const float4*)(Bp + 12);
            Ap += 32; Bp += 32;
        }
    };
    auto sstore = [&](int buf) {
        if (TRANS == 0) {
            // pack rows (2sk, 2sk+1) -> kpair sk ; rows (2sk+16, 2sk+17) -> kpair sk+8
            *(uint4*)&As[buf][sk][sm] = make_uint4(
                pack_bf2(ra0.x, ra1.x), pack_bf2(ra0.y, ra1.y),
                pack_bf2(ra0.z, ra1.z), pack_bf2(ra0.w, ra1.w));
            *(uint4*)&As[buf][sk + 8][sm] = make_uint4(
                pack_bf2(ra2.x, ra3.x), pack_bf2(ra2.y, ra3.y),
                pack_bf2(ra2.z, ra3.z), pack_bf2(ra2.w, ra3.w));
            *(uint4*)&Bs[buf][sk][sm] = make_uint4(
                pack_bf2(rb0.x, rb1.x), pack_bf2(rb0.y, rb1.y),
                pack_bf2(rb0.z, rb1.z), pack_bf2(rb0.w, rb1.w));
            *(uint4*)&Bs[buf][sk + 8][sm] = make_uint4(
                pack_bf2(rb2.x, rb3.x), pack_bf2(rb2.y, rb3.y),
                pack_bf2(rb2.z, rb3.z), pack_bf2(rb2.w, rb3.w));
        } else {
            const int kp = sk >> 1;   // 0 or 8
            As[buf][kp + 0][sm] = pack_bf2(ra0.x, ra0.y);
            As[buf][kp + 1][sm] = pack_bf2(ra0.z, ra0.w);
            As[buf][kp + 2][sm] = pack_bf2(ra1.x, ra1.y);
            As[buf][kp + 3][sm] = pack_bf2(ra1.z, ra1.w);
            As[buf][kp + 4][sm] = pack_bf2(ra2.x, ra2.y);
            As[buf][kp + 5][sm] = pack_bf2(ra2.z, ra2.w);
            As[buf][kp + 6][sm] = pack_bf2(ra3.x, ra3.y);
            As[buf][kp + 7][sm] = pack_bf2(ra3.z, ra3.w);
            Bs[buf][kp + 0][sm] = pack_bf2(rb0.x, rb0.y);
            Bs[buf][kp + 1][sm] = pack_bf2(rb0.z, rb0.w);
            Bs[buf][kp + 2][sm] = pack_bf2(rb1.x, rb1.y);
            Bs[buf][kp + 3][sm] = pack_bf2(rb1.z, rb1.w);
            Bs[buf][kp + 4][sm] = pack_bf2(rb2.x, rb2.y);
            Bs[buf][kp + 5][sm] = pack_bf2(rb2.z, rb2.w);
            Bs[buf][kp + 6][sm] = pack_bf2(rb3.x, rb3.y);
            Bs[buf][kp + 7][sm] = pack_bf2(rb3.z, rb3.w);
        }
    };

    const int nIt = K >> 5;          // k-tile 32
    gload();
    sstore(0);
    __syncthreads();

    for (int it = 0; it < nIt; ++it) {
        const int buf = it & 1;
        if (it + 1 < nIt) gload();

        #pragma unroll
        for (int s = 0; s < 2; ++s) {
            const int kb = s * 8;    // kpair base: covers k = 16s .. 16s+15
            unsigned af[4][4], bf[4][2];
            #pragma unroll
            for (int j = 0; j < 4; ++j) {
                bf[j][0] = Bs[buf][kb + t    ][wn + j * 8 + g];
                bf[j][1] = Bs[buf][kb + t + 4][wn + j * 8 + g];
            }
            #pragma unroll
            for (int i = 0; i < 4; ++i) {
                const int mb = wm + i * 16;
                af[i][0] = As[buf][kb + t    ][mb + g];
                af[i][1] = As[buf][kb + t    ][mb + g + 8];
                af[i][2] = As[buf][kb + t + 4][mb + g];
                af[i][3] = As[buf][kb + t + 4][mb + g + 8];
            }
            #pragma unroll
            for (int i = 0; i < 4; ++i)
                #pragma unroll
                for (int j = 0; j < 4; ++j)
                    mma_bf16(acc[i][j], af[i], bf[j]);
        }

        if (it + 1 < nIt) {
            sstore(buf ^ 1);
            __syncthreads();
        }
    }

    // epilogue
    #pragma unroll
    for (int i = 0; i < 4; ++i) {
        const int r0 = m0 + wm + i * 16 + g;
        const int r1 = r0 + 8;
        float bv0 = 0.f, bv1 = 0.f;
        if (EPI != 1) { bv0 = bias[r0]; bv1 = bias[r1]; }
        #pragma unroll
        for (int j = 0; j < 4; ++j) {
            const int cc = n0 + wn + j * 8 + 2 * t;
            const float* d = acc[i][j];
            if (EPI == 0) {
                *(float2*)&C[(size_t)r0 * ldc + cc] = make_float2(d[0] + bv0, d[1] + bv0);
                *(float2*)&C[(size_t)r1 * ldc + cc] = make_float2(d[2] + bv1, d[3] + bv1);
            } else if (EPI == 1) {
                *(float2*)&C[(size_t)r0 * ldc + cc] = make_float2(d[0] * scale, d[1] * scale);
                *(float2*)&C[(size_t)r1 * ldc + cc] = make_float2(d[2] * scale, d[3] * scale);
            } else {
                const float2 x0 = *(const float2*)&res[(size_t)r0 * ldc + cc];
                const float2 x1 = *(const float2*)&res[(size_t)r1 * ldc + cc];
                *(float2*)&C[(size_t)r0 * ldc + cc] =
                    make_float2((d[0] + bv0 + x0.x) * scale, (d[1] + bv0 + x0.y) * scale);
                *(float2*)&C[(size_t)r1 * ldc + cc] =
                    make_float2((d[2] + bv1 + x1.x) * scale, (d[3] + bv1 + x1.y) * scale);
            }
        }
    }
}

// ---------------- Row softmax over N_=4096, in place, float4 paths.
__global__ __launch_bounds__(256) void softmax_kernel(float* __restrict__ w)
{
    __shared__ float4 buf[N_ / 4];
    __shared__ float red[8];
    float4* p = (float4*)(w + (size_t)blockIdx.x * N_);
    const int t = threadIdx.x;

    float mx = -1e30f;
    #pragma unroll
    for (int i = t; i < N_ / 4; i += 256) {
        float4 v = p[i]; buf[i] = v;
        mx = fmaxf(mx, fmaxf(fmaxf(v.x, v.y), fmaxf(v.z, v.w)));
    }
    #pragma unroll
    for (int o = 16; o; o >>= 1) mx = fmaxf(mx, __shfl_xor_sync(0xffffffffu, mx, o));
    if ((t & 31) == 0) red[t >> 5] = mx;
    __syncthreads();
    mx = red[0];
    #pragma unroll
    for (int i = 1; i < 8; i++) mx = fmaxf(mx, red[i]);

    float s = 0.f;
    #pragma unroll
    for (int i = t; i < N_ / 4; i += 256) {
        float4 v = buf[i];
        v.x = __expf(v.x - mx); v.y = __expf(v.y - mx);
        v.z = __expf(v.z - mx); v.w = __expf(v.w - mx);
        buf[i] = v;
        s += (v.x + v.y) + (v.z + v.w);
    }
    #pragma unroll
    for (int o = 16; o; o >>= 1) s += __shfl_xor_sync(0xffffffffu, s, o);
    __syncthreads();
    if ((t & 31) == 0) red[t >> 5] = s;
    __syncthreads();
    s = 0.f;
    #pragma unroll
    for (int i = 0; i < 8; i++) s += red[i];

    const float inv = 1.f / s;
    #pragma unroll
    for (int i = t; i < N_ / 4; i += 256) {
        float4 v = buf[i];
        p[i] = make_float4(v.x * inv, v.y * inv, v.z * inv, v.w * inv);
    }
}

// ---------------- launch ----------------
extern "C" void kernel_launch(void* const* d_in, const int* in_sizes, int n_in,
                              void* d_out, int out_size)
{
    const float* x    = (const float*)d_in[0];
    const float* gn_w = (const float*)d_in[1];
    const float* gn_b = (const float*)d_in[2];
    const float* Wq   = (const float*)d_in[3];
    const float* bq   = (const float*)d_in[4];
    const float* Wk   = (const float*)d_in[5];
    const float* bk   = (const float*)d_in[6];
    const float* Wv   = (const float*)d_in[7];
    const float* bv   = (const float*)d_in[8];
    const float* Wp   = (const float*)d_in[9];
    const float* bp   = (const float*)d_in[10];
    float* out = (float*)d_out;

    float *ph, *pq, *pk, *pv, *patt, *pw;
    cudaGetSymbolAddress((void**)&ph,   g_h);
    cudaGetSymbolAddress((void**)&pq,   g_q);
    cudaGetSymbolAddress((void**)&pk,   g_k);
    cudaGetSymbolAddress((void**)&pv,   g_v);
    cudaGetSymbolAddress((void**)&patt, g_att);
    cudaGetSymbolAddress((void**)&pw,   g_w);

    const size_t chw = (size_t)C_ * N_;   // per-batch [C, HW]
    const size_t nn  = (size_t)N_ * N_;   // per-batch logits

    // 1) GroupNorm
    gn_kernel<<<B_ * G_, 256>>>(x, gn_w, gn_b, ph);

    // 2) Q, K, V projections: q[d][n] = sum_c W[c][d] * h[c][n] + b[d]
    {
        dim3 grid(N_ / 128, C_ / 128, B_);
        mma_gemm<0, 0><<<grid, 256>>>(Wq, ph, pq, bq, nullptr, 0, chw, chw,
                                      C_, N_, N_, C_, 0.f);
        mma_gemm<0, 0><<<grid, 256>>>(Wk, ph, pk, bk, nullptr, 0, chw, chw,
                                      C_, N_, N_, C_, 0.f);
        mma_gemm<0, 0><<<grid, 256>>>(Wv, ph, pv, bv, nullptr, 0, chw, chw,
                                      C_, N_, N_, C_, 0.f);
    }

    // 3) logits: w[n][m] = (1/16) * sum_c q[c][n] * k[c][m]
    {
        dim3 grid(N_ / 128, N_ / 128, B_);
        mma_gemm<0, 1><<<grid, 256>>>(pq, pk, pw, nullptr, nullptr, chw, chw, nn,
                                      N_, N_, N_, C_, 0.0625f);
    }

    // 4) softmax rows (in place)
    softmax_kernel<<<B_ * N_, 256>>>(pw);

    // 5) att[c][n] = sum_m v[c][m] * w[n][m]   (k = spatial m)
    {
        dim3 grid(N_ / 128, C_ / 128, B_);
        mma_gemm<1, 1><<<grid, 256>>>(pv, pw, patt, nullptr, nullptr, chw, nn, chw,
                                      N_, N_, N_, N_, 1.0f);
    }

    // 6) out = (x + Wp^T att + bp) / sqrt(2)
    {
        dim3 grid(N_ / 128, C_ / 128, B_);
        mma_gemm<0, 2><<<grid, 256>>>(Wp, patt, out, bp, x, 0, chw, chw,
                                      C_, N_, N_, C_, 0.70710678118654752f);
    }
}

// round 16
// speedup vs baseline: 1.4856x; 1.0004x over previous
#include <cuda_runtime.h>
#include <cuda_bf16.h>
#include <math.h>

// Problem constants (fixed shapes per reference)
#define B_   4
#define C_   256
#define N_   4096      // H*W
#define G_   32        // groups
#define CPG_ 8         // channels per group

// ---------------- scratch (device globals; no allocation) ----------------
__device__ float g_h  [(size_t)B_ * C_ * N_];   // groupnorm output
__device__ float g_q  [(size_t)B_ * C_ * N_];
__device__ float g_k  [(size_t)B_ * C_ * N_];
__device__ float g_v  [(size_t)B_ * C_ * N_];
__device__ float g_att[(size_t)B_ * C_ * N_];   // softmax(w) @ v
__device__ float g_w  [(size_t)B_ * N_ * N_];   // attention logits / weights (268 MB)

// ---------------- helpers ----------------
// pack two fp32 -> bf16x2 (lo = first/even-k, hi = second/odd-k)
__device__ __forceinline__ unsigned pack_bf2(float lo, float hi) {
    __nv_bfloat162 h = __float22bfloat162_rn(make_float2(lo, hi));
    return *reinterpret_cast<unsigned*>(&h);
}

__device__ __forceinline__ void mma_bf16(float* d, const unsigned* a, const unsigned* b) {
    asm volatile(
        "mma.sync.aligned.m16n8k16.row.col.f32.bf16.bf16.f32 "
        "{%0,%1,%2,%3}, {%4,%5,%6,%7}, {%8,%9}, {%0,%1,%2,%3};"
        : "+f"(d[0]), "+f"(d[1]), "+f"(d[2]), "+f"(d[3])
        : "r"(a[0]), "r"(a[1]), "r"(a[2]), "r"(a[3]), "r"(b[0]), "r"(b[1]));
}

// ---------------- GroupNorm ----------------
__global__ __launch_bounds__(256) void gn_kernel(
    const float* __restrict__ x, const float* __restrict__ w,
    const float* __restrict__ b, float* __restrict__ out)
{
    const int bg = blockIdx.x;
    const int bb = bg / G_;
    const int g  = bg % G_;
    const float* xp = x   + ((size_t)bb * C_ + (size_t)g * CPG_) * N_;
    float*       op = out + ((size_t)bb * C_ + (size_t)g * CPG_) * N_;
    const int NE = CPG_ * N_;  // 32768

    float s = 0.f, ss = 0.f;
    for (int i = threadIdx.x; i < NE; i += 256) {
        float v = xp[i];
        s += v; ss += v * v;
    }
    __shared__ float rs[8], rss[8];
    #pragma unroll
    for (int o = 16; o; o >>= 1) {
        s  += __shfl_xor_sync(0xffffffffu, s,  o);
        ss += __shfl_xor_sync(0xffffffffu, ss, o);
    }
    if ((threadIdx.x & 31) == 0) { rs[threadIdx.x >> 5] = s; rss[threadIdx.x >> 5] = ss; }
    __syncthreads();
    s = 0.f; ss = 0.f;
    #pragma unroll
    for (int i = 0; i < 8; i++) { s += rs[i]; ss += rss[i]; }

    const float invn = 1.0f / (float)NE;
    const float mean = s * invn;
    const float var  = ss * invn - mean * mean;
    const float inv  = rsqrtf(var + 1e-5f);

    for (int i = threadIdx.x; i < NE; i += 256) {
        int c = g * CPG_ + i / N_;
        op[i] = (xp[i] - mean) * inv * w[c] + b[c];
    }
}

// ---------------- bf16 tensor-core GEMM ----------------
// TRANS=0 ("kk"):  C[m][n] = epi( sum_k A[k][m] * B[k][n] )   (k-major operands)
// TRANS=1 ("nt"):  C[m][n] = epi( sum_k A[m][k] * B[n][k] )   (k-contiguous rows)
// EPI: 0 = +bias[m] ; 1 = *scale ; 2 = (acc + bias[m] + res[m][n]) * scale
// Block tile 128x128, k-tile 32, 256 threads = 8 warps (2M x 4N), warp 64x32.
// Smem holds bf16 pairs packed in uint32 at [kpair][m], pitch 136 (conflict-free:
// fragment bank = 8t+g, bijective over the warp).
#define PITCH 136

template<int TRANS, int EPI>
__global__ __launch_bounds__(256, 2) void mma_gemm(
    const float* __restrict__ A, const float* __restrict__ B,
    float* __restrict__ C, const float* __restrict__ bias,
    const float* __restrict__ res,
    size_t aStride, size_t bStride, size_t cStride,
    int lda, int ldb, int ldc, int K, float scale)
{
    A += (size_t)blockIdx.z * aStride;
    B += (size_t)blockIdx.z * bStride;
    C += (size_t)blockIdx.z * cStride;
    if (EPI == 2) res += (size_t)blockIdx.z * cStride;

    __shared__ unsigned As[2][16][PITCH];   // 16 kpairs (k-tile 32)
    __shared__ unsigned Bs[2][16][PITCH];

    const int tid  = threadIdx.x;
    const int lane = tid & 31;
    const int warp = tid >> 5;
    const int g = lane >> 2;        // 0..7
    const int t = lane & 3;         // 0..3
    const int wm = (warp & 1) * 64; // warp M offset
    const int wn = (warp >> 1) * 32;// warp N offset
    const int m0 = blockIdx.y * 128;
    const int n0 = blockIdx.x * 128;

    float acc[4][4][4] = {};
    float4 ra0, ra1, ra2, ra3, rb0, rb1, rb2, rb3;

    // loader coordinates
    int sk, sm;
    const float *Ap, *Bp;
    if (TRANS == 0) {
        sk = tid >> 5;            // kpair row 0..7 (also +8)
        sm = (tid & 31) * 4;      // m/n column (float4)
        Ap = A + (size_t)(2 * sk) * lda + m0 + sm;
        Bp = B + (size_t)(2 * sk) * ldb + n0 + sm;
    } else {
        sm = tid >> 1;            // tile row 0..127
        sk = (tid & 1) * 16;      // k base 0 or 16
        Ap = A + (size_t)(m0 + sm) * lda + sk;
        Bp = B + (size_t)(n0 + sm) * ldb + sk;
    }

    auto gload = [&]() {
        if (TRANS == 0) {
            ra0 = *(const float4*)Ap;
            ra1 = *(const float4*)(Ap + (size_t)lda);
            ra2 = *(const float4*)(Ap + (size_t)16 * lda);
            ra3 = *(const float4*)(Ap + (size_t)17 * lda);
            rb0 = *(const float4*)Bp;
            rb1 = *(const float4*)(Bp + (size_t)ldb);
            rb2 = *(const float4*)(Bp + (size_t)16 * ldb);
            rb3 = *(const float4*)(Bp + (size_t)17 * ldb);
            Ap += (size_t)32 * lda;
            Bp += (size_t)32 * ldb;
        } else {
            ra0 = *(const float4*)Ap;
            ra1 = *(const float4*)(Ap + 4);
            ra2 = *(const float4*)(Ap + 8);
            ra3 = *(const float4*)(Ap + 12);
            rb0 = *(const float4*)Bp;
            rb1 = *(const float4*)(Bp + 4);
            rb2 = *(const float4*)(Bp + 8);
            rb3 = *(const float4*)(Bp + 12);
            Ap += 32; Bp += 32;
        }
    };
    auto sstore = [&](int buf) {
        if (TRANS == 0) {
            // pack rows (2sk, 2sk+1) -> kpair sk ; rows (2sk+16, 2sk+17) -> kpair sk+8
            *(uint4*)&As[buf][sk][sm] = make_uint4(
                pack_bf2(ra0.x, ra1.x), pack_bf2(ra0.y, ra1.y),
                pack_bf2(ra0.z, ra1.z), pack_bf2(ra0.w, ra1.w));
            *(uint4*)&As[buf][sk + 8][sm] = make_uint4(
                pack_bf2(ra2.x, ra3.x), pack_bf2(ra2.y, ra3.y),
                pack_bf2(ra2.z, ra3.z), pack_bf2(ra2.w, ra3.w));
            *(uint4*)&Bs[buf][sk][sm] = make_uint4(
                pack_bf2(rb0.x, rb1.x), pack_bf2(rb0.y, rb1.y),
                pack_bf2(rb0.z, rb1.z), pack_bf2(rb0.w, rb1.w));
            *(uint4*)&Bs[buf][sk + 8][sm] = make_uint4(
                pack_bf2(rb2.x, rb3.x), pack_bf2(rb2.y, rb3.y),
                pack_bf2(rb2.z, rb3.z), pack_bf2(rb2.w, rb3.w));
        } else {
            const int kp = sk >> 1;   // 0 or 8
            As[buf][kp + 0][sm] = pack_bf2(ra0.x, ra0.y);
            As[buf][kp + 1][sm] = pack_bf2(ra0.z, ra0.w);
            As[buf][kp + 2][sm] = pack_bf2(ra1.x, ra1.y);
            As[buf][kp + 3][sm] = pack_bf2(ra1.z, ra1.w);
            As[buf][kp + 4][sm] = pack_bf2(ra2.x, ra2.y);
            As[buf][kp + 5][sm] = pack_bf2(ra2.z, ra2.w);
            As[buf][kp + 6][sm] = pack_bf2(ra3.x, ra3.y);
            As[buf][kp + 7][sm] = pack_bf2(ra3.z, ra3.w);
            Bs[buf][kp + 0][sm] = pack_bf2(rb0.x, rb0.y);
            Bs[buf][kp + 1][sm] = pack_bf2(rb0.z, rb0.w);
            Bs[buf][kp + 2][sm] = pack_bf2(rb1.x, rb1.y);
            Bs[buf][kp + 3][sm] = pack_bf2(rb1.z, rb1.w);
            Bs[buf][kp + 4][sm] = pack_bf2(rb2.x, rb2.y);
            Bs[buf][kp + 5][sm] = pack_bf2(rb2.z, rb2.w);
            Bs[buf][kp + 6][sm] = pack_bf2(rb3.x, rb3.y);
            Bs[buf][kp + 7][sm] = pack_bf2(rb3.z, rb3.w);
        }
    };

    const int nIt = K >> 5;          // k-tile 32
    gload();
    sstore(0);
    __syncthreads();

    for (int it = 0; it < nIt; ++it) {
        const int buf = it & 1;
        if (it + 1 < nIt) gload();

        #pragma unroll
        for (int s = 0; s < 2; ++s) {
            const int kb = s * 8;    // kpair base: covers k = 16s .. 16s+15
            unsigned af[4][4], bf[4][2];
            #pragma unroll
            for (int j = 0; j < 4; ++j) {
                bf[j][0] = Bs[buf][kb + t    ][wn + j * 8 + g];
                bf[j][1] = Bs[buf][kb + t + 4][wn + j * 8 + g];
            }
            #pragma unroll
            for (int i = 0; i < 4; ++i) {
                const int mb = wm + i * 16;
                af[i][0] = As[buf][kb + t    ][mb + g];
                af[i][1] = As[buf][kb + t    ][mb + g + 8];
                af[i][2] = As[buf][kb + t + 4][mb + g];
                af[i][3] = As[buf][kb + t + 4][mb + g + 8];
            }
            #pragma unroll
            for (int i = 0; i < 4; ++i)
                #pragma unroll
                for (int j = 0; j < 4; ++j)
                    mma_bf16(acc[i][j], af[i], bf[j]);
        }

        if (it + 1 < nIt) {
            sstore(buf ^ 1);
            __syncthreads();
        }
    }

    // epilogue
    #pragma unroll
    for (int i = 0; i < 4; ++i) {
        const int r0 = m0 + wm + i * 16 + g;
        const int r1 = r0 + 8;
        float bv0 = 0.f, bv1 = 0.f;
        if (EPI != 1) { bv0 = bias[r0]; bv1 = bias[r1]; }
        #pragma unroll
        for (int j = 0; j < 4; ++j) {
            const int cc = n0 + wn + j * 8 + 2 * t;
            const float* d = acc[i][j];
            if (EPI == 0) {
                *(float2*)&C[(size_t)r0 * ldc + cc] = make_float2(d[0] + bv0, d[1] + bv0);
                *(float2*)&C[(size_t)r1 * ldc + cc] = make_float2(d[2] + bv1, d[3] + bv1);
            } else if (EPI == 1) {
                *(float2*)&C[(size_t)r0 * ldc + cc] = make_float2(d[0] * scale, d[1] * scale);
                *(float2*)&C[(size_t)r1 * ldc + cc] = make_float2(d[2] * scale, d[3] * scale);
            } else {
                const float2 x0 = *(const float2*)&res[(size_t)r0 * ldc + cc];
                const float2 x1 = *(const float2*)&res[(size_t)r1 * ldc + cc];
                *(float2*)&C[(size_t)r0 * ldc + cc] =
                    make_float2((d[0] + bv0 + x0.x) * scale, (d[1] + bv0 + x0.y) * scale);
                *(float2*)&C[(size_t)r1 * ldc + cc] =
                    make_float2((d[2] + bv1 + x1.x) * scale, (d[3] + bv1 + x1.y) * scale);
            }
        }
    }
}

// ---------------- Row softmax over N_=4096, in place, float4 paths.
__global__ __launch_bounds__(256) void softmax_kernel(float* __restrict__ w)
{
    __shared__ float4 buf[N_ / 4];
    __shared__ float red[8];
    float4* p = (float4*)(w + (size_t)blockIdx.x * N_);
    const int t = threadIdx.x;

    float mx = -1e30f;
    #pragma unroll
    for (int i = t; i < N_ / 4; i += 256) {
        float4 v = p[i]; buf[i] = v;
        mx = fmaxf(mx, fmaxf(fmaxf(v.x, v.y), fmaxf(v.z, v.w)));
    }
    #pragma unroll
    for (int o = 16; o; o >>= 1) mx = fmaxf(mx, __shfl_xor_sync(0xffffffffu, mx, o));
    if ((t & 31) == 0) red[t >> 5] = mx;
    __syncthreads();
    mx = red[0];
    #pragma unroll
    for (int i = 1; i < 8; i++) mx = fmaxf(mx, red[i]);

    float s = 0.f;
    #pragma unroll
    for (int i = t; i < N_ / 4; i += 256) {
        float4 v = buf[i];
        v.x = __expf(v.x - mx); v.y = __expf(v.y - mx);
        v.z = __expf(v.z - mx); v.w = __expf(v.w - mx);
        buf[i] = v;
        s += (v.x + v.y) + (v.z + v.w);
    }
    #pragma unroll
    for (int o = 16; o; o >>= 1) s += __shfl_xor_sync(0xffffffffu, s, o);
    __syncthreads();
    if ((t & 31) == 0) red[t >> 5] = s;
    __syncthreads();
    s = 0.f;
    #pragma unroll
    for (int i = 0; i < 8; i++) s += red[i];

    const float inv = 1.f / s;
    #pragma unroll
    for (int i = t; i < N_ / 4; i += 256) {
        float4 v = buf[i];
        p[i] = make_float4(v.x * inv, v.y * inv, v.z * inv, v.w * inv);
    }
}

// ---------------- launch ----------------
extern "C" void kernel_launch(void* const* d_in, const int* in_sizes, int n_in,
                              void* d_out, int out_size)
{
    const float* x    = (const float*)d_in[0];
    const float* gn_w = (const float*)d_in[1];
    const float* gn_b = (const float*)d_in[2];
    const float* Wq   = (const float*)d_in[3];
    const float* bq   = (const float*)d_in[4];
    const float* Wk   = (const float*)d_in[5];
    const float* bk   = (const float*)d_in[6];
    const float* Wv   = (const float*)d_in[7];
    const float* bv   = (const float*)d_in[8];
    const float* Wp   = (const float*)d_in[9];
    const float* bp   = (const float*)d_in[10];
    float* out = (float*)d_out;

    float *ph, *pq, *pk, *pv, *patt, *pw;
    cudaGetSymbolAddress((void**)&ph,   g_h);
    cudaGetSymbolAddress((void**)&pq,   g_q);
    cudaGetSymbolAddress((void**)&pk,   g_k);
    cudaGetSymbolAddress((void**)&pv,   g_v);
    cudaGetSymbolAddress((void**)&patt, g_att);
    cudaGetSymbolAddress((void**)&pw,   g_w);

    const size_t chw = (size_t)C_ * N_;   // per-batch [C, HW]
    const size_t nn  = (size_t)N_ * N_;   // per-batch logits

    // 1) GroupNorm
    gn_kernel<<<B_ * G_, 256>>>(x, gn_w, gn_b, ph);

    // 2) Q, K, V projections: q[d][n] = sum_c W[c][d] * h[c][n] + b[d]
    {
        dim3 grid(N_ / 128, C_ / 128, B_);
        mma_gemm<0, 0><<<grid, 256>>>(Wq, ph, pq, bq, nullptr, 0, chw, chw,
                                      C_, N_, N_, C_, 0.f);
        mma_gemm<0, 0><<<grid, 256>>>(Wk, ph, pk, bk, nullptr, 0, chw, chw,
                                      C_, N_, N_, C_, 0.f);
        mma_gemm<0, 0><<<grid, 256>>>(Wv, ph, pv, bv, nullptr, 0, chw, chw,
                                      C_, N_, N_, C_, 0.f);
    }

    // 3) logits: w[n][m] = (1/16) * sum_c q[c][n] * k[c][m]
    {
        dim3 grid(N_ / 128, N_ / 128, B_);
        mma_gemm<0, 1><<<grid, 256>>>(pq, pk, pw, nullptr, nullptr, chw, chw, nn,
                                      N_, N_, N_, C_, 0.0625f);
    }

    // 4) softmax rows (in place)
    softmax_kernel<<<B_ * N_, 256>>>(pw);

    // 5) att[c][n] = sum_m v[c][m] * w[n][m]   (k = spatial m)
    {
        dim3 grid(N_ / 128, C_ / 128, B_);
        mma_gemm<1, 1><<<grid, 256>>>(pv, pw, patt, nullptr, nullptr, chw, nn, chw,
                                      N_, N_, N_, N_, 1.0f);
    }

    // 6) out = (x + Wp^T att + bp) / sqrt(2)
    {
        dim3 grid(N_ / 128, C_ / 128, B_);
        mma_gemm<0, 2><<<grid, 256>>>(Wp, patt, out, bp, x, 0, chw, chw,
                                      C_, N_, N_, C_, 0.70710678118654752f);
    }
}